// round 10
// baseline (speedup 1.0000x reference)
#include <cuda_runtime.h>
#include <cstdint>
#include <math.h>

#define NSITE 524288          // 32*32*32*16
#define TILE  128
#define NTILES (NSITE / TILE) // 4096
#define NT    512             // 16 warps, one 8-col n-tile each
#define GRID  148

// SMEM float offsets (fragment-resident layouts)
#define XF_OFF  0             // X frags:  [m][ks][lane][r]  8*8*32*4   = 8192
#define HF_OFF  8192          // H frags:  [mlp][m][ks2][lane][r] 2*8*16*32*4 = 32768
#define SP0_OFF 40960         // head partials: 2 x 16*128
#define SAR_OFF 45056         // AR dots: 128
#define SMEM_FLOATS 45184
#define SMEM_BYTES (SMEM_FLOATS * 4)

__device__ float g_nn[NSITE];
__device__ float g_W1w[16384];              // [W1;W1n]*diag(weight), tf32
__device__ float g_W2w[32768];              // [W2;W2n], tf32
__device__ __align__(16) float  g_b1ext[256];
__device__ __align__(16) float2 g_c2 [128];   // (b2, w3)
__device__ __align__(16) float2 g_c2n[128];   // (b2n, w3n)

static __device__ __forceinline__ uint32_t f2tf(float x) {
    uint32_t r; asm("cvt.rna.tf32.f32 %0, %1;" : "=r"(r) : "f"(x)); return r;
}
static __device__ __forceinline__ float tanha(float x) {
    float y; asm("tanh.approx.f32 %0, %1;" : "=f"(y) : "f"(x)); return y;
}
static __device__ __forceinline__ void mma_tf32(
    float& c0, float& c1, float& c2, float& c3,
    uint32_t a0, uint32_t a1, uint32_t a2, uint32_t a3,
    uint32_t b0, uint32_t b1)
{
    asm volatile(
        "mma.sync.aligned.m16n8k8.row.col.f32.tf32.tf32.f32 "
        "{%0,%1,%2,%3}, {%4,%5,%6,%7}, {%8,%9}, {%0,%1,%2,%3};"
        : "+f"(c0), "+f"(c1), "+f"(c2), "+f"(c3)
        : "r"(a0), "r"(a1), "r"(a2), "r"(a3), "r"(b0), "r"(b1));
}

__global__ __launch_bounds__(NT, 1)
void fnn_mma_kernel(
    const float* __restrict__ x_in, const float* __restrict__ ag,
    const float* __restrict__ b3,  const float* __restrict__ b3n,
    const float* __restrict__ max_os_l,
    float* __restrict__ out_os)
{
    extern __shared__ float sm[];
    const int tid = threadIdx.x;
    const int wid = tid >> 5;       // 0..15 -> n-tile / GEMM2 k-block
    const int lid = tid & 31;
    const int g   = lid >> 2;
    const int t   = lid & 3;
    const int n0  = wid * 8;

    const float maxos = expf(max_os_l[0]);
    const float b3v = b3[0], b3nv = b3n[0];

    // per-warp bias / head constants (persistent, small)
    const float2 bv0 = *(const float2*)(g_b1ext + n0 + 2*t);
    const float2 bv1 = *(const float2*)(g_b1ext + 128 + n0 + 2*t);
    const float4 cw0 = *(const float4*)(&g_c2 [n0 + 2*t]);
    const float4 cw1 = *(const float4*)(&g_c2n[n0 + 2*t]);
    // staging constants: this thread always handles cols cst..cst+3
    const int cst = (tid & 15) * 4;
    const float4 ag4 = *(const float4*)(ag + cst);
    // B fragment base pointers (fixed addresses -> L1-resident after tile 1)
    const float* w1p = g_W1w + (size_t)(n0 + g) * 64;          // + mlp*8192
    const float* w2p = g_W2w + (size_t)(n0 + g) * 128;         // + mlp*16384

    for (int tile = blockIdx.x; tile < NTILES; tile += GRID) {
        const int base = tile * TILE;

        // ---- B1 fragments for this tile (L1 hits; not live across tiles) ----
        uint32_t B1[2][16];
        #pragma unroll
        for (int mlp = 0; mlp < 2; mlp++) {
            const float* wp = w1p + mlp * 8192;
            #pragma unroll
            for (int ks = 0; ks < 8; ks++) {
                B1[mlp][ks*2+0] = __float_as_uint(__ldg(wp + ks*8 + t));
                B1[mlp][ks*2+1] = __float_as_uint(__ldg(wp + ks*8 + t + 4));
            }
        }

        // ---- stage X into fragment layout + AR dot ----
        #pragma unroll
        for (int it = 0; it < 4; it++) {
            int row = (tid >> 4) + it * 32;          // 0..127
            float4 v = *(const float4*)(x_in + (size_t)(base + row) * 64 + cst);
            float pr = v.x*ag4.x + v.y*ag4.y + v.z*ag4.z + v.w*ag4.w;
            pr += __shfl_xor_sync(0xffffffffu, pr, 8);
            pr += __shfl_xor_sync(0xffffffffu, pr, 4);
            pr += __shfl_xor_sync(0xffffffffu, pr, 2);
            pr += __shfl_xor_sync(0xffffffffu, pr, 1);
            if ((tid & 15) == 0) sm[SAR_OFF + row] = pr;
            int m  = row >> 4, gg = row & 7, hi = (row >> 3) & 1;
            int ks = cst >> 3;
            int r  = hi + ((cst & 4) >> 1);          // hi + 2*hi4
            float* p = sm + XF_OFF + m*1024 + ks*128 + gg*16 + r;
            p[0]  = __uint_as_float(f2tf(v.x));
            p[4]  = __uint_as_float(f2tf(v.y));
            p[8]  = __uint_as_float(f2tf(v.z));
            p[12] = __uint_as_float(f2tf(v.w));
        }
        __syncthreads();   // S1

        // ---- fused GEMM1 (both MLPs): H = tanh(X W1'^T + b1) in frag layout ----
        #pragma unroll
        for (int m = 0; m < 8; m++) {
            const float* ap = sm + XF_OFF + m*1024 + lid*4;
            uint4 A[8];
            #pragma unroll
            for (int ks = 0; ks < 8; ks++) A[ks] = *(const uint4*)(ap + ks*128);
            float oa0=0,oa1=0,oa2=0,oa3=0, ob0=0,ob1=0,ob2=0,ob3=0;
            float na0=0,na1=0,na2=0,na3=0, nb0=0,nb1=0,nb2=0,nb3=0;
            #pragma unroll
            for (int ks = 0; ks < 8; ks += 2) {
                mma_tf32(oa0,oa1,oa2,oa3, A[ks].x,A[ks].y,A[ks].z,A[ks].w,
                         B1[0][ks*2], B1[0][ks*2+1]);
                mma_tf32(na0,na1,na2,na3, A[ks].x,A[ks].y,A[ks].z,A[ks].w,
                         B1[1][ks*2], B1[1][ks*2+1]);
                mma_tf32(ob0,ob1,ob2,ob3, A[ks+1].x,A[ks+1].y,A[ks+1].z,A[ks+1].w,
                         B1[0][ks*2+2], B1[0][ks*2+3]);
                mma_tf32(nb0,nb1,nb2,nb3, A[ks+1].x,A[ks+1].y,A[ks+1].z,A[ks+1].w,
                         B1[1][ks*2+2], B1[1][ks*2+3]);
            }
            // consecutive floats = rows {g, g+8} of the SAME column:
            //   l0 -> col 2t : (h0, h2) ; l1 -> col 2t+1 : (h1, h3)
            const int l0 = 16*g + 4*((2*t)   & 3) + 2*(((2*t)   >> 2));
            const int l1 = 16*g + 4*((2*t+1) & 3) + 2*(((2*t+1) >> 2));
            {   // os
                float h0 = __uint_as_float(f2tf(tanha(oa0+ob0 + bv0.x)));
                float h1 = __uint_as_float(f2tf(tanha(oa1+ob1 + bv0.y)));
                float h2 = __uint_as_float(f2tf(tanha(oa2+ob2 + bv0.x)));
                float h3 = __uint_as_float(f2tf(tanha(oa3+ob3 + bv0.y)));
                float* hp = sm + HF_OFF + m*2048 + wid*128;
                *(float2*)(hp + l0) = make_float2(h0, h2);
                *(float2*)(hp + l1) = make_float2(h1, h3);
            }
            {   // nn
                float h0 = __uint_as_float(f2tf(tanha(na0+nb0 + bv1.x)));
                float h1 = __uint_as_float(f2tf(tanha(na1+nb1 + bv1.y)));
                float h2 = __uint_as_float(f2tf(tanha(na2+nb2 + bv1.x)));
                float h3 = __uint_as_float(f2tf(tanha(na3+nb3 + bv1.y)));
                float* hp = sm + HF_OFF + 16384 + m*2048 + wid*128;
                *(float2*)(hp + l0) = make_float2(h0, h2);
                *(float2*)(hp + l1) = make_float2(h1, h3);
            }
        }
        __syncthreads();   // S2

        // ---- GEMM2 + heads (unroll 1: keep only one mlp's B2 live) ----
        #pragma unroll 1
        for (int mlp = 0; mlp < 2; mlp++) {
            const float4 cw = mlp ? cw1 : cw0;
            float* sP = sm + SP0_OFF + mlp * 2048;

            uint32_t B2[32];
            {
                const float* wp2 = w2p + mlp * 16384;
                #pragma unroll
                for (int ks = 0; ks < 16; ks++) {
                    B2[ks*2+0] = __float_as_uint(__ldg(wp2 + ks*8 + t));
                    B2[ks*2+1] = __float_as_uint(__ldg(wp2 + ks*8 + t + 4));
                }
            }

            #pragma unroll
            for (int m = 0; m < 8; m++) {
                const float* ap = sm + HF_OFF + mlp*16384 + m*2048 + lid*4;
                float a0=0,a1=0,a2=0,a3=0, e0=0,e1=0,e2=0,e3=0;
                #pragma unroll
                for (int half = 0; half < 2; half++) {
                    uint4 A[8];
                    #pragma unroll
                    for (int ks = 0; ks < 8; ks++)
                        A[ks] = *(const uint4*)(ap + (half*8 + ks)*128);
                    #pragma unroll
                    for (int ks = 0; ks < 8; ks += 2) {
                        const int kk = half*8 + ks;
                        mma_tf32(a0,a1,a2,a3, A[ks].x,A[ks].y,A[ks].z,A[ks].w,
                                 B2[kk*2], B2[kk*2+1]);
                        mma_tf32(e0,e1,e2,e3, A[ks+1].x,A[ks+1].y,A[ks+1].z,A[ks+1].w,
                                 B2[kk*2+2], B2[kk*2+3]);
                    }
                }
                float c0=a0+e0, c1=a1+e1, c2=a2+e2, c3=a3+e3;
                float sum0 = tanha(c0 + cw.x)*cw.y + tanha(c1 + cw.z)*cw.w;
                float sum1 = tanha(c2 + cw.x)*cw.y + tanha(c3 + cw.z)*cw.w;
                sum0 += __shfl_xor_sync(0xffffffffu, sum0, 1);
                sum0 += __shfl_xor_sync(0xffffffffu, sum0, 2);
                sum1 += __shfl_xor_sync(0xffffffffu, sum1, 1);
                sum1 += __shfl_xor_sync(0xffffffffu, sum1, 2);
                if (t == 0) {
                    sP[wid*128 + m*16 + g]     = sum0;
                    sP[wid*128 + m*16 + g + 8] = sum1;
                }
            }
            __syncthreads();   // S3 (mlp0) / S4 (mlp1)

            if (tid < 128) {
                float s = 0.f;
                #pragma unroll
                for (int w = 0; w < 16; w++) s += sP[w*128 + tid];
                float val = tanhf(s + (mlp ? b3nv : b3v)) * maxos;
                if (mlp == 0) out_os[base + tid] = val + sm[SAR_OFF + tid];
                else          g_nn  [base + tid] = val;
            }
        }
        __syncthreads();   // protect SAR/XF/HF/SP before next tile
    }
}

// ---- prep: fold weight into W1, tf32-round B matrices, pack constants ----
__global__ void fnn_prep_kernel(
    const float* __restrict__ W1,  const float* __restrict__ W1n,
    const float* __restrict__ weight,
    const float* __restrict__ W2,  const float* __restrict__ W2n,
    const float* __restrict__ b1,  const float* __restrict__ b1n,
    const float* __restrict__ b2,  const float* __restrict__ w3,
    const float* __restrict__ b2n, const float* __restrict__ w3n)
{
    int idx = blockIdx.x * blockDim.x + threadIdx.x;   // 32768 threads
    if (idx < 16384) {
        int n = idx >> 6, k = idx & 63;
        float v = (n < 128 ? W1[n * 64 + k] : W1n[(n - 128) * 64 + k]) * weight[k];
        g_W1w[idx] = __uint_as_float(f2tf(v));
    }
    g_W2w[idx] = __uint_as_float(f2tf(idx < 16384 ? W2[idx] : W2n[idx - 16384]));
    if (idx < 128) {
        g_b1ext[idx]       = b1[idx];
        g_b1ext[128 + idx] = b1n[idx];
        g_c2 [idx] = make_float2(b2[idx],  w3[idx]);
        g_c2n[idx] = make_float2(b2n[idx], w3n[idx]);
    }
}

// ---- stencil + sigma ----
__global__ void fnn_stencil_kernel(const float* __restrict__ sigma_l,
                                   float* __restrict__ out)
{
    int idx = blockIdx.x * blockDim.x + threadIdx.x;
    if (idx >= NSITE) return;
    const int ib = idx & 15;
    const int iz = (idx >> 4)  & 31;
    const int iy = (idx >> 9)  & 31;
    const int ix = (idx >> 14) & 31;
    const int xm = (ix + 31) & 31, xp = (ix + 1) & 31;
    const int ym = (iy + 31) & 31, yp = (iy + 1) & 31;
    const int zm = (iz + 31) & 31, zp = (iz + 1) & 31;
#define FNN_I(a, b, c) ((((((a) << 5) + (b)) << 5) + (c)) * 16 + ib)
    float s =
        g_nn[FNN_I(xm, iy, zm)] + g_nn[FNN_I(xm, iy, zp)] +
        g_nn[FNN_I(xp, iy, zm)] + g_nn[FNN_I(xp, iy, zp)] +
        g_nn[FNN_I(ix, ym, zm)] + g_nn[FNN_I(ix, ym, zp)] +
        g_nn[FNN_I(ix, yp, zm)] + g_nn[FNN_I(ix, yp, zp)];
#undef FNN_I
    out[idx] += 0.125f * s;
    out[NSITE + idx] = expf(sigma_l[0]);
}

extern "C" void kernel_launch(void* const* d_in, const int* in_sizes, int n_in,
                              void* d_out, int out_size)
{
    const float* x_in     = (const float*)d_in[0];
    const float* weight   = (const float*)d_in[1];
    const float* ag       = (const float*)d_in[2];
    const float* W1       = (const float*)d_in[3];
    const float* b1       = (const float*)d_in[4];
    const float* W2       = (const float*)d_in[5];
    const float* b2       = (const float*)d_in[6];
    const float* W3       = (const float*)d_in[7];
    const float* b3       = (const float*)d_in[8];
    const float* W1n      = (const float*)d_in[9];
    const float* b1n      = (const float*)d_in[10];
    const float* W2n      = (const float*)d_in[11];
    const float* b2n      = (const float*)d_in[12];
    const float* W3n      = (const float*)d_in[13];
    const float* b3n      = (const float*)d_in[14];
    const float* max_os_l = (const float*)d_in[15];
    const float* sigma_l  = (const float*)d_in[16];
    float* out = (float*)d_out;

    fnn_prep_kernel<<<128, 256>>>(W1, W1n, weight, W2, W2n,
                                  b1, b1n, b2, W3, b2n, W3n);

    cudaFuncSetAttribute(fnn_mma_kernel,
                         cudaFuncAttributeMaxDynamicSharedMemorySize, SMEM_BYTES);
    fnn_mma_kernel<<<GRID, NT, SMEM_BYTES>>>(
        x_in, ag, b3, b3n, max_os_l, out);

    fnn_stencil_kernel<<<NSITE / 256, 256>>>(sigma_l, out);
}

// round 13
// speedup vs baseline: 3.0104x; 3.0104x over previous
#include <cuda_runtime.h>
#include <cuda_fp16.h>
#include <cstdint>
#include <math.h>

#define NSITE 524288          // 32*32*32*16
#define TILE  128
#define NTILES (NSITE / TILE) // 4096
#define NT    512             // 16 warps
#define GRID  148

// SMEM word (float) offsets
#define XF_OFF  0             // X frags fp16: [m][ks4][lane][4w] = 4096 words (16 KB)
#define HF_OFF  4096          // H frags fp16: [mlp][m][ks8][lane][4w] = 16384 words (64 KB)
#define SP_OFF  20480         // head partials: [mlp][8][128] = 2048 words
#define SAR_OFF 22528         // AR dots: 128 words
#define SMEM_FLOATS 22656
#define SMEM_BYTES (SMEM_FLOATS * 4)

__device__ float  g_nn[NSITE];
__device__ __half g_W1h[16384];             // [W1;W1n]*diag(weight), fp16  [256][64]
__device__ __half g_W2h[32768];             // [W2;W2n], fp16               [256][128]
__device__ __align__(16) float  g_b1ext[256];
__device__ __align__(16) float2 g_c2 [128];   // (b2, w3)
__device__ __align__(16) float2 g_c2n[128];   // (b2n, w3n)

static __device__ __forceinline__ float tanha(float x) {
    float y; asm("tanh.approx.f32 %0, %1;" : "=f"(y) : "f"(x)); return y;
}
// m16n8k16 fp16 mma, fp32 accum
static __device__ __forceinline__ void mma_f16(
    float& c0, float& c1, float& c2, float& c3,
    uint32_t a0, uint32_t a1, uint32_t a2, uint32_t a3,
    uint32_t b0, uint32_t b1)
{
    asm volatile(
        "mma.sync.aligned.m16n8k16.row.col.f32.f16.f16.f32 "
        "{%0,%1,%2,%3}, {%4,%5,%6,%7}, {%8,%9}, {%0,%1,%2,%3};"
        : "+f"(c0), "+f"(c1), "+f"(c2), "+f"(c3)
        : "r"(a0), "r"(a1), "r"(a2), "r"(a3), "r"(b0), "r"(b1));
}
static __device__ __forceinline__ uint32_t h2u(__half2 h) {
    uint32_t u; *(__half2*)&u = h; return u;
}

__global__ __launch_bounds__(NT, 1)
void fnn_mma_kernel(
    const float* __restrict__ x_in, const float* __restrict__ ag,
    const float* __restrict__ b3,  const float* __restrict__ b3n,
    const float* __restrict__ max_os_l,
    float* __restrict__ out_os)
{
    extern __shared__ float sm[];
    const int tid = threadIdx.x;
    const int wid = tid >> 5;       // 0..15
    const int lid = tid & 31;
    const int g   = lid >> 2;
    const int t   = lid & 3;

    // GEMM1/GEMM2 warp role: mlp = wid>>3, 16-col group (wid&7)
    const int mlp = wid >> 3;
    const int cg  = wid & 7;            // col-group (16 cols) within mlp
    const int nb  = cg * 16;

    const float maxos = expf(max_os_l[0]);
    const float b3v = b3[0], b3nv = b3n[0];

    // ---- persistent B fragments (fp16: 16 + 32 = 48 regs) ----
    uint32_t B1r[2][8];     // [j][ks*2 + half]
    uint32_t B2r[2][16];
    #pragma unroll
    for (int j = 0; j < 2; j++) {
        const __half* wp = g_W1h + (size_t)(mlp*128 + nb + 8*j + g) * 64;
        #pragma unroll
        for (int ks = 0; ks < 4; ks++) {
            B1r[j][ks*2+0] = *(const uint32_t*)(wp + ks*16 + 2*t);
            B1r[j][ks*2+1] = *(const uint32_t*)(wp + ks*16 + 2*t + 8);
        }
        const __half* wp2 = g_W2h + (size_t)(mlp*128 + nb + 8*j + g) * 128;
        #pragma unroll
        for (int ks = 0; ks < 8; ks++) {
            B2r[j][ks*2+0] = *(const uint32_t*)(wp2 + ks*16 + 2*t);
            B2r[j][ks*2+1] = *(const uint32_t*)(wp2 + ks*16 + 2*t + 8);
        }
    }
    // bias / head constants for this warp's columns
    float2 bv[2]; float4 cw[2];
    #pragma unroll
    for (int j = 0; j < 2; j++) {
        int c0 = nb + 8*j + 2*t;
        bv[j] = *(const float2*)(g_b1ext + mlp*128 + c0);
        cw[j] = *(const float4*)((mlp ? g_c2n : g_c2) + c0);  // (b2,w3,b2',w3')
    }
    // staging constants
    const int cst = (tid & 15) * 4;     // this thread's 4 columns
    const float4 ag4 = *(const float4*)(ag + cst);
    const int s_ks = cst >> 4;                       // k-step
    const int s_u  = (cst & 15) >> 1;                // unit index {0,2,4,6}
    const int s_t  = s_u & 3;                        // target t (even)
    const int s_kh = s_u >> 2;                       // k-half -> +2 in word idx

    for (int tile = blockIdx.x; tile < NTILES; tile += GRID) {
        const int base = tile * TILE;

        // ---- stage X (fp16 fragment layout) + AR dot ----
        #pragma unroll
        for (int it = 0; it < 4; it++) {
            int row = (tid >> 4) + it * 32;          // 0..127
            float4 v = *(const float4*)(x_in + (size_t)(base + row) * 64 + cst);
            float pr = v.x*ag4.x + v.y*ag4.y + v.z*ag4.z + v.w*ag4.w;
            pr += __shfl_xor_sync(0xffffffffu, pr, 8);
            pr += __shfl_xor_sync(0xffffffffu, pr, 4);
            pr += __shfl_xor_sync(0xffffffffu, pr, 2);
            pr += __shfl_xor_sync(0xffffffffu, pr, 1);
            if ((tid & 15) == 0) sm[SAR_OFF + row] = pr;
            int m = row >> 4, gg = row & 7, hi = (row >> 3) & 1;
            int r = hi + 2*s_kh;
            float* p = sm + XF_OFF + m*512 + s_ks*128 + (gg*4 + s_t)*4 + r;
            *(__half2*)(p)     = __floats2half2_rn(v.x, v.y);
            *(__half2*)(p + 4) = __floats2half2_rn(v.z, v.w);   // t+1 slot
        }
        __syncthreads();   // S1

        // ---- GEMM1: H = tanh(X @ W1'^T + b1), K=64 (4 k-steps) ----
        #pragma unroll
        for (int m = 0; m < 8; m++) {
            const float* ap = sm + XF_OFF + m*512 + lid*4;
            uint4 A[4];
            #pragma unroll
            for (int ks = 0; ks < 4; ks++) A[ks] = *(const uint4*)(ap + ks*128);
            float a00=0,a01=0,a02=0,a03=0, a10=0,a11=0,a12=0,a13=0;
            #pragma unroll
            for (int ks = 0; ks < 4; ks++) {
                mma_f16(a00,a01,a02,a03, A[ks].x,A[ks].y,A[ks].z,A[ks].w,
                        B1r[0][ks*2], B1r[0][ks*2+1]);
                mma_f16(a10,a11,a12,a13, A[ks].x,A[ks].y,A[ks].z,A[ks].w,
                        B1r[1][ks*2], B1r[1][ks*2+1]);
            }
            // D layout: c0=(g,2t) c1=(g,2t+1) c2=(g+8,2t) c3=(g+8,2t+1)
            uint4 hw;
            hw.x = h2u(__floats2half2_rn(tanha(a00 + bv[0].x), tanha(a01 + bv[0].y)));
            hw.y = h2u(__floats2half2_rn(tanha(a02 + bv[0].x), tanha(a03 + bv[0].y)));
            hw.z = h2u(__floats2half2_rn(tanha(a10 + bv[1].x), tanha(a11 + bv[1].y)));
            hw.w = h2u(__floats2half2_rn(tanha(a12 + bv[1].x), tanha(a13 + bv[1].y)));
            // one STS.128: words {j0hi0, j0hi1, j1hi0, j1hi1} at consumer frag addr
            *(uint4*)(sm + HF_OFF + mlp*8192 + m*1024 + cg*128 + lid*4) = hw;
        }
        __syncthreads();   // S2

        // ---- GEMM2: head partials, K=128 (8 k-steps) ----
        #pragma unroll
        for (int m = 0; m < 8; m++) {
            const float* ap = sm + HF_OFF + mlp*8192 + m*1024 + lid*4;
            float a00=0,a01=0,a02=0,a03=0, a10=0,a11=0,a12=0,a13=0;
            #pragma unroll
            for (int half2_ = 0; half2_ < 2; half2_++) {
                uint4 A[4];
                #pragma unroll
                for (int ks = 0; ks < 4; ks++)
                    A[ks] = *(const uint4*)(ap + (half2_*4 + ks)*128);
                #pragma unroll
                for (int ks = 0; ks < 4; ks++) {
                    const int kk = half2_*4 + ks;
                    mma_f16(a00,a01,a02,a03, A[ks].x,A[ks].y,A[ks].z,A[ks].w,
                            B2r[0][kk*2], B2r[0][kk*2+1]);
                    mma_f16(a10,a11,a12,a13, A[ks].x,A[ks].y,A[ks].z,A[ks].w,
                            B2r[1][kk*2], B2r[1][kk*2+1]);
                }
            }
            float sum0 = tanha(a00 + cw[0].x)*cw[0].y + tanha(a01 + cw[0].z)*cw[0].w
                       + tanha(a10 + cw[1].x)*cw[1].y + tanha(a11 + cw[1].z)*cw[1].w;
            float sum1 = tanha(a02 + cw[0].x)*cw[0].y + tanha(a03 + cw[0].z)*cw[0].w
                       + tanha(a12 + cw[1].x)*cw[1].y + tanha(a13 + cw[1].z)*cw[1].w;
            sum0 += __shfl_xor_sync(0xffffffffu, sum0, 1);
            sum0 += __shfl_xor_sync(0xffffffffu, sum0, 2);
            sum1 += __shfl_xor_sync(0xffffffffu, sum1, 1);
            sum1 += __shfl_xor_sync(0xffffffffu, sum1, 2);
            if (t == 0) {
                sm[SP_OFF + mlp*1024 + cg*128 + m*16 + g]     = sum0;
                sm[SP_OFF + mlp*1024 + cg*128 + m*16 + g + 8] = sum1;
            }
        }
        __syncthreads();   // S3

        // ---- heads: both mlps in parallel (threads 0-255) ----
        if (tid < 256) {
            int hm   = tid >> 7;       // 0: os, 1: nn
            int site = tid & 127;
            float s = 0.f;
            #pragma unroll
            for (int p = 0; p < 8; p++) s += sm[SP_OFF + hm*1024 + p*128 + site];
            float val = tanhf(s + (hm ? b3nv : b3v)) * maxos;
            if (hm == 0) out_os[base + site] = val + sm[SAR_OFF + site];
            else         g_nn  [base + site] = val;
        }
        __syncthreads();   // S4: protect XF/HF/SP/SAR before next tile
    }
}

// ---- prep: fold weight into W1, fp16-convert B matrices, pack constants ----
__global__ void fnn_prep_kernel(
    const float* __restrict__ W1,  const float* __restrict__ W1n,
    const float* __restrict__ weight,
    const float* __restrict__ W2,  const float* __restrict__ W2n,
    const float* __restrict__ b1,  const float* __restrict__ b1n,
    const float* __restrict__ b2,  const float* __restrict__ w3,
    const float* __restrict__ b2n, const float* __restrict__ w3n)
{
    int idx = blockIdx.x * blockDim.x + threadIdx.x;   // 32768 threads
    if (idx < 16384) {
        int n = idx >> 6, k = idx & 63;
        float v = (n < 128 ? W1[n * 64 + k] : W1n[(n - 128) * 64 + k]) * weight[k];
        g_W1h[idx] = __float2half_rn(v);
    }
    g_W2h[idx] = __float2half_rn(idx < 16384 ? W2[idx] : W2n[idx - 16384]);
    if (idx < 128) {
        g_b1ext[idx]       = b1[idx];
        g_b1ext[128 + idx] = b1n[idx];
        g_c2 [idx] = make_float2(b2[idx],  w3[idx]);
        g_c2n[idx] = make_float2(b2n[idx], w3n[idx]);
    }
}

// ---- stencil + sigma ----
__global__ void fnn_stencil_kernel(const float* __restrict__ sigma_l,
                                   float* __restrict__ out)
{
    int idx = blockIdx.x * blockDim.x + threadIdx.x;
    if (idx >= NSITE) return;
    const int ib = idx & 15;
    const int iz = (idx >> 4)  & 31;
    const int iy = (idx >> 9)  & 31;
    const int ix = (idx >> 14) & 31;
    const int xm = (ix + 31) & 31, xp = (ix + 1) & 31;
    const int ym = (iy + 31) & 31, yp = (iy + 1) & 31;
    const int zm = (iz + 31) & 31, zp = (iz + 1) & 31;
#define FNN_I(a, b, c) ((((((a) << 5) + (b)) << 5) + (c)) * 16 + ib)
    float s =
        g_nn[FNN_I(xm, iy, zm)] + g_nn[FNN_I(xm, iy, zp)] +
        g_nn[FNN_I(xp, iy, zm)] + g_nn[FNN_I(xp, iy, zp)] +
        g_nn[FNN_I(ix, ym, zm)] + g_nn[FNN_I(ix, ym, zp)] +
        g_nn[FNN_I(ix, yp, zm)] + g_nn[FNN_I(ix, yp, zp)];
#undef FNN_I
    out[idx] += 0.125f * s;
    out[NSITE + idx] = expf(sigma_l[0]);
}

extern "C" void kernel_launch(void* const* d_in, const int* in_sizes, int n_in,
                              void* d_out, int out_size)
{
    const float* x_in     = (const float*)d_in[0];
    const float* weight   = (const float*)d_in[1];
    const float* ag       = (const float*)d_in[2];
    const float* W1       = (const float*)d_in[3];
    const float* b1       = (const float*)d_in[4];
    const float* W2       = (const float*)d_in[5];
    const float* b2       = (const float*)d_in[6];
    const float* W3       = (const float*)d_in[7];
    const float* b3       = (const float*)d_in[8];
    const float* W1n      = (const float*)d_in[9];
    const float* b1n      = (const float*)d_in[10];
    const float* W2n      = (const float*)d_in[11];
    const float* b2n      = (const float*)d_in[12];
    const float* W3n      = (const float*)d_in[13];
    const float* b3n      = (const float*)d_in[14];
    const float* max_os_l = (const float*)d_in[15];
    const float* sigma_l  = (const float*)d_in[16];
    float* out = (float*)d_out;

    fnn_prep_kernel<<<128, 256>>>(W1, W1n, weight, W2, W2n,
                                  b1, b1n, b2, W3, b2n, W3n);

    cudaFuncSetAttribute(fnn_mma_kernel,
                         cudaFuncAttributeMaxDynamicSharedMemorySize, SMEM_BYTES);
    fnn_mma_kernel<<<GRID, NT, SMEM_BYTES>>>(
        x_in, ag, b3, b3n, max_os_l, out);

    fnn_stencil_kernel<<<NSITE / 256, 256>>>(sigma_l, out);
}

// round 14
// speedup vs baseline: 3.0745x; 1.0213x over previous
#include <cuda_runtime.h>
#include <cuda_fp16.h>
#include <cstdint>
#include <math.h>

#define NSITE 524288          // 32*32*32*16
#define TILE  128
#define NTILES (NSITE / TILE) // 4096
#define NT    256             // 8 warps, 32 cols each
#define GRID  148

// SMEM word (float) offsets
#define XF_OFF  0             // X frags fp16: [m][ks4][lane][4w] = 4096 words (16 KB)
#define HF_OFF  4096          // H frags fp16: [mlp][m][ks8][lane][4w] = 16384 words (64 KB)
#define SP_OFF  20480         // head partials: [mlp][4][128] = 1024 words
#define SAR_OFF 21504         // AR dots: 128 words
#define SMEM_FLOATS 21632
#define SMEM_BYTES (SMEM_FLOATS * 4)

__device__ float  g_nn[NSITE];
__device__ __half g_W1h[16384];             // [W1;W1n]*diag(weight), fp16  [256][64]
__device__ __half g_W2h[32768];             // [W2;W2n], fp16               [256][128]
__device__ __align__(16) float  g_b1ext[256];
__device__ __align__(16) float2 g_c2 [128];   // (b2, w3)
__device__ __align__(16) float2 g_c2n[128];   // (b2n, w3n)

static __device__ __forceinline__ float tanha(float x) {
    float y; asm("tanh.approx.f32 %0, %1;" : "=f"(y) : "f"(x)); return y;
}
static __device__ __forceinline__ void mma_f16(
    float& c0, float& c1, float& c2, float& c3,
    uint32_t a0, uint32_t a1, uint32_t a2, uint32_t a3,
    uint32_t b0, uint32_t b1)
{
    asm volatile(
        "mma.sync.aligned.m16n8k16.row.col.f32.f16.f16.f32 "
        "{%0,%1,%2,%3}, {%4,%5,%6,%7}, {%8,%9}, {%0,%1,%2,%3};"
        : "+f"(c0), "+f"(c1), "+f"(c2), "+f"(c3)
        : "r"(a0), "r"(a1), "r"(a2), "r"(a3), "r"(b0), "r"(b1));
}
static __device__ __forceinline__ uint32_t h2u(__half2 h) {
    uint32_t u; *(__half2*)&u = h; return u;
}

__global__ __launch_bounds__(NT, 1)
void fnn_mma_kernel(
    const float* __restrict__ x_in, const float* __restrict__ ag,
    const float* __restrict__ b3,  const float* __restrict__ b3n,
    const float* __restrict__ max_os_l,
    float* __restrict__ out_os)
{
    extern __shared__ float sm[];
    const int tid = threadIdx.x;
    const int wid = tid >> 5;       // 0..7
    const int lid = tid & 31;
    const int g   = lid >> 2;
    const int t   = lid & 3;

    const int mlp = wid >> 2;       // 0..1
    const int cg  = wid & 3;        // 32-col group within mlp
    const int nb  = cg * 32;

    const float maxos = expf(max_os_l[0]);
    const float b3v = b3[0], b3nv = b3n[0];

    // ---- persistent B fragments (fp16: 32 + 64 = 96 regs) ----
    uint32_t B1r[4][8];
    uint32_t B2r[4][16];
    #pragma unroll
    for (int j = 0; j < 4; j++) {
        const __half* wp = g_W1h + (size_t)(mlp*128 + nb + 8*j + g) * 64;
        #pragma unroll
        for (int ks = 0; ks < 4; ks++) {
            B1r[j][ks*2+0] = *(const uint32_t*)(wp + ks*16 + 2*t);
            B1r[j][ks*2+1] = *(const uint32_t*)(wp + ks*16 + 2*t + 8);
        }
        const __half* wp2 = g_W2h + (size_t)(mlp*128 + nb + 8*j + g) * 128;
        #pragma unroll
        for (int ks = 0; ks < 8; ks++) {
            B2r[j][ks*2+0] = *(const uint32_t*)(wp2 + ks*16 + 2*t);
            B2r[j][ks*2+1] = *(const uint32_t*)(wp2 + ks*16 + 2*t + 8);
        }
    }
    // bias / head constants
    float2 bv[4]; float4 cw[4];
    #pragma unroll
    for (int j = 0; j < 4; j++) {
        int c0 = nb + 8*j + 2*t;
        bv[j] = *(const float2*)(g_b1ext + mlp*128 + c0);
        cw[j] = *(const float4*)((mlp ? g_c2n : g_c2) + c0);
    }
    // staging constants
    const int cst = (tid & 15) * 4;
    const float4 ag4 = *(const float4*)(ag + cst);
    const int s_ks = cst >> 4;
    const int s_u  = (cst & 15) >> 1;
    const int s_t  = s_u & 3;
    const int s_kh = s_u >> 2;

    // ---- prefetch first tile into registers ----
    float4 vreg[8];
    int tile = blockIdx.x;
    if (tile < NTILES) {
        #pragma unroll
        for (int it = 0; it < 8; it++) {
            int row = (tid >> 4) + it * 16;
            vreg[it] = *(const float4*)(x_in + (size_t)(tile*TILE + row) * 64 + cst);
        }
    }

    for (; tile < NTILES; tile += GRID) {
        const int base = tile * TILE;

        // ---- stage X from prefetched regs + AR dot ----
        #pragma unroll
        for (int it = 0; it < 8; it++) {
            int row = (tid >> 4) + it * 16;
            float4 v = vreg[it];
            float pr = v.x*ag4.x + v.y*ag4.y + v.z*ag4.z + v.w*ag4.w;
            pr += __shfl_xor_sync(0xffffffffu, pr, 8);
            pr += __shfl_xor_sync(0xffffffffu, pr, 4);
            pr += __shfl_xor_sync(0xffffffffu, pr, 2);
            pr += __shfl_xor_sync(0xffffffffu, pr, 1);
            if ((tid & 15) == 0) sm[SAR_OFF + row] = pr;
            int m = row >> 4, gg = row & 7, hi = (row >> 3) & 1;
            int r = hi + 2*s_kh;
            float* p = sm + XF_OFF + m*512 + s_ks*128 + (gg*4 + s_t)*4 + r;
            *(__half2*)(p)     = __floats2half2_rn(v.x, v.y);
            *(__half2*)(p + 4) = __floats2half2_rn(v.z, v.w);
        }
        __syncthreads();   // S1

        // ---- prefetch next tile (overlaps GEMM1/GEMM2) ----
        {
            int nt_ = tile + GRID;
            if (nt_ < NTILES) {
                #pragma unroll
                for (int it = 0; it < 8; it++) {
                    int row = (tid >> 4) + it * 16;
                    vreg[it] = *(const float4*)(x_in + (size_t)(nt_*TILE + row) * 64 + cst);
                }
            }
        }

        // ---- GEMM1: H = tanh(X @ W1'^T + b1), K=64, 4 j-chains ----
        #pragma unroll
        for (int m = 0; m < 8; m++) {
            const float* ap = sm + XF_OFF + m*512 + lid*4;
            uint4 A[4];
            #pragma unroll
            for (int ks = 0; ks < 4; ks++) A[ks] = *(const uint4*)(ap + ks*128);
            float acc[4][4];
            #pragma unroll
            for (int j = 0; j < 4; j++)
                acc[j][0]=acc[j][1]=acc[j][2]=acc[j][3]=0.f;
            #pragma unroll
            for (int ks = 0; ks < 4; ks++) {
                #pragma unroll
                for (int j = 0; j < 4; j++)
                    mma_f16(acc[j][0],acc[j][1],acc[j][2],acc[j][3],
                            A[ks].x,A[ks].y,A[ks].z,A[ks].w,
                            B1r[j][ks*2], B1r[j][ks*2+1]);
            }
            // pack: j-pair jp covers consumer k-step 2*cg+jp
            #pragma unroll
            for (int jp = 0; jp < 2; jp++) {
                const int j0 = 2*jp, j1 = 2*jp + 1;
                uint4 hw;
                hw.x = h2u(__floats2half2_rn(tanha(acc[j0][0] + bv[j0].x),
                                             tanha(acc[j0][1] + bv[j0].y)));
                hw.y = h2u(__floats2half2_rn(tanha(acc[j0][2] + bv[j0].x),
                                             tanha(acc[j0][3] + bv[j0].y)));
                hw.z = h2u(__floats2half2_rn(tanha(acc[j1][0] + bv[j1].x),
                                             tanha(acc[j1][1] + bv[j1].y)));
                hw.w = h2u(__floats2half2_rn(tanha(acc[j1][2] + bv[j1].x),
                                             tanha(acc[j1][3] + bv[j1].y)));
                *(uint4*)(sm + HF_OFF + mlp*8192 + m*1024 + (2*cg + jp)*128 + lid*4) = hw;
            }
        }
        __syncthreads();   // S2

        // ---- GEMM2: head partials, K=128, 4 j-chains ----
        #pragma unroll
        for (int m = 0; m < 8; m++) {
            const float* ap = sm + HF_OFF + mlp*8192 + m*1024 + lid*4;
            float acc[4][4];
            #pragma unroll
            for (int j = 0; j < 4; j++)
                acc[j][0]=acc[j][1]=acc[j][2]=acc[j][3]=0.f;
            #pragma unroll
            for (int half_ = 0; half_ < 2; half_++) {
                uint4 A[4];
                #pragma unroll
                for (int ks = 0; ks < 4; ks++)
                    A[ks] = *(const uint4*)(ap + (half_*4 + ks)*128);
                #pragma unroll
                for (int ks = 0; ks < 4; ks++) {
                    const int kk = half_*4 + ks;
                    #pragma unroll
                    for (int j = 0; j < 4; j++)
                        mma_f16(acc[j][0],acc[j][1],acc[j][2],acc[j][3],
                                A[ks].x,A[ks].y,A[ks].z,A[ks].w,
                                B2r[j][kk*2], B2r[j][kk*2+1]);
                }
            }
            float sum0 = 0.f, sum1 = 0.f;
            #pragma unroll
            for (int j = 0; j < 4; j++) {
                sum0 += tanha(acc[j][0] + cw[j].x)*cw[j].y
                      + tanha(acc[j][1] + cw[j].z)*cw[j].w;
                sum1 += tanha(acc[j][2] + cw[j].x)*cw[j].y
                      + tanha(acc[j][3] + cw[j].z)*cw[j].w;
            }
            sum0 += __shfl_xor_sync(0xffffffffu, sum0, 1);
            sum0 += __shfl_xor_sync(0xffffffffu, sum0, 2);
            sum1 += __shfl_xor_sync(0xffffffffu, sum1, 1);
            sum1 += __shfl_xor_sync(0xffffffffu, sum1, 2);
            if (t == 0) {
                sm[SP_OFF + mlp*512 + cg*128 + m*16 + g]     = sum0;
                sm[SP_OFF + mlp*512 + cg*128 + m*16 + g + 8] = sum1;
            }
        }
        __syncthreads();   // S3

        // ---- heads: both mlps in parallel (all 256 threads) ----
        {
            int hm   = tid >> 7;       // 0: os, 1: nn
            int site = tid & 127;
            float s = 0.f;
            #pragma unroll
            for (int p = 0; p < 4; p++) s += sm[SP_OFF + hm*512 + p*128 + site];
            float val = tanhf(s + (hm ? b3nv : b3v)) * maxos;
            if (hm == 0) out_os[base + site] = val + sm[SAR_OFF + site];
            else         g_nn  [base + site] = val;
        }
        __syncthreads();   // S4
    }
}

// ---- prep: fold weight into W1, fp16-convert B matrices, pack constants ----
__global__ void fnn_prep_kernel(
    const float* __restrict__ W1,  const float* __restrict__ W1n,
    const float* __restrict__ weight,
    const float* __restrict__ W2,  const float* __restrict__ W2n,
    const float* __restrict__ b1,  const float* __restrict__ b1n,
    const float* __restrict__ b2,  const float* __restrict__ w3,
    const float* __restrict__ b2n, const float* __restrict__ w3n)
{
    int idx = blockIdx.x * blockDim.x + threadIdx.x;   // 32768 threads
    if (idx < 16384) {
        int n = idx >> 6, k = idx & 63;
        float v = (n < 128 ? W1[n * 64 + k] : W1n[(n - 128) * 64 + k]) * weight[k];
        g_W1h[idx] = __float2half_rn(v);
    }
    g_W2h[idx] = __float2half_rn(idx < 16384 ? W2[idx] : W2n[idx - 16384]);
    if (idx < 128) {
        g_b1ext[idx]       = b1[idx];
        g_b1ext[128 + idx] = b1n[idx];
        g_c2 [idx] = make_float2(b2[idx],  w3[idx]);
        g_c2n[idx] = make_float2(b2n[idx], w3n[idx]);
    }
}

// ---- stencil + sigma ----
__global__ void fnn_stencil_kernel(const float* __restrict__ sigma_l,
                                   float* __restrict__ out)
{
    int idx = blockIdx.x * blockDim.x + threadIdx.x;
    if (idx >= NSITE) return;
    const int ib = idx & 15;
    const int iz = (idx >> 4)  & 31;
    const int iy = (idx >> 9)  & 31;
    const int ix = (idx >> 14) & 31;
    const int xm = (ix + 31) & 31, xp = (ix + 1) & 31;
    const int ym = (iy + 31) & 31, yp = (iy + 1) & 31;
    const int zm = (iz + 31) & 31, zp = (iz + 1) & 31;
#define FNN_I(a, b, c) ((((((a) << 5) + (b)) << 5) + (c)) * 16 + ib)
    float s =
        g_nn[FNN_I(xm, iy, zm)] + g_nn[FNN_I(xm, iy, zp)] +
        g_nn[FNN_I(xp, iy, zm)] + g_nn[FNN_I(xp, iy, zp)] +
        g_nn[FNN_I(ix, ym, zm)] + g_nn[FNN_I(ix, ym, zp)] +
        g_nn[FNN_I(ix, yp, zm)] + g_nn[FNN_I(ix, yp, zp)];
#undef FNN_I
    out[idx] += 0.125f * s;
    out[NSITE + idx] = expf(sigma_l[0]);
}

extern "C" void kernel_launch(void* const* d_in, const int* in_sizes, int n_in,
                              void* d_out, int out_size)
{
    const float* x_in     = (const float*)d_in[0];
    const float* weight   = (const float*)d_in[1];
    const float* ag       = (const float*)d_in[2];
    const float* W1       = (const float*)d_in[3];
    const float* b1       = (const float*)d_in[4];
    const float* W2       = (const float*)d_in[5];
    const float* b2       = (const float*)d_in[6];
    const float* W3       = (const float*)d_in[7];
    const float* b3       = (const float*)d_in[8];
    const float* W1n      = (const float*)d_in[9];
    const float* b1n      = (const float*)d_in[10];
    const float* W2n      = (const float*)d_in[11];
    const float* b2n      = (const float*)d_in[12];
    const float* W3n      = (const float*)d_in[13];
    const float* b3n      = (const float*)d_in[14];
    const float* max_os_l = (const float*)d_in[15];
    const float* sigma_l  = (const float*)d_in[16];
    float* out = (float*)d_out;

    fnn_prep_kernel<<<128, 256>>>(W1, W1n, weight, W2, W2n,
                                  b1, b1n, b2, W3, b2n, W3n);

    cudaFuncSetAttribute(fnn_mma_kernel,
                         cudaFuncAttributeMaxDynamicSharedMemorySize, SMEM_BYTES);
    fnn_mma_kernel<<<GRID, NT, SMEM_BYTES>>>(
        x_in, ag, b3, b3n, max_os_l, out);

    fnn_stencil_kernel<<<NSITE / 256, 256>>>(sigma_l, out);
}